// round 7
// baseline (speedup 1.0000x reference)
#include <cuda_runtime.h>
#include <cstdint>

// Problem constants (fixed by setup_inputs: N=64, T=400, D=1024, M=256)
#define NTOK 25600
#define DDIM 1024
#define MCOD 256
#define ROWS_PER_BLK 64
#define KT 32          // floats per k-tile
#define KP 16          // bf16 pairs per k-tile
#define NPAIR 512      // DDIM/2 pairs per code row
#define MARGIN 0.5f

typedef unsigned long long u64;

// ---------------- packed bf16x2 helpers (sm_80+, not "a"-gated) ----------------
static __device__ __forceinline__ uint32_t bf2(float lo, float hi) {
    uint32_t r;  // cvt packs first source into the UPPER half
    asm("cvt.rn.bf16x2.f32 %0, %1, %2;" : "=r"(r) : "f"(hi), "f"(lo));
    return r;
}
static __device__ __forceinline__ uint32_t bffma2(uint32_t a, uint32_t b, uint32_t c) {
    uint32_t d;
    asm("fma.rn.bf16x2 %0, %1, %2, %3;" : "=r"(d) : "r"(a), "r"(b), "r"(c));
    return d;
}

// ---------------- device scratch (allocation-free per harness rules) ----------------
__device__ float    g_enorm[MCOD * DDIM];   // fp32 normalized codebook (exact pass)
__device__ uint32_t g_ebf[MCOD * NPAIR];    // packed bf16 pairs of g_enorm
__device__ float    g_se[MCOD];
__device__ int      g_counts[MCOD];
__device__ double   g_loss;

// ---------------------------------------------------------------------------
// Zero accumulators (must run every launch: graph replays reuse globals)
// ---------------------------------------------------------------------------
__global__ void vq_init() {
    int t = threadIdx.x;
    g_counts[t] = 0;
    if (t == 0) g_loss = 0.0;
}

// ---------------------------------------------------------------------------
// emb_norm[m] = emb[m] / (||emb[m]|| + 1e-4);  se[m] = sum(emb_norm[m]^2)
// Also emits the packed bf16 image of emb_norm for the screening GEMM.
// ---------------------------------------------------------------------------
__global__ __launch_bounds__(256) void vq_normalize(const float* __restrict__ emb) {
    __shared__ float red[256];
    const int m = blockIdx.x;
    const int t = threadIdx.x;

    float4 v = ((const float4*)(emb + (size_t)m * DDIM))[t];
    float p = v.x * v.x + v.y * v.y + v.z * v.z + v.w * v.w;
    red[t] = p;
    __syncthreads();
    for (int s = 128; s > 0; s >>= 1) {
        if (t < s) red[t] += red[t + s];
        __syncthreads();
    }
    float denom = __fadd_rn(sqrtf(red[0]), 1e-4f);
    __syncthreads();

    float4 e;
    e.x = __fdiv_rn(v.x, denom);
    e.y = __fdiv_rn(v.y, denom);
    e.z = __fdiv_rn(v.z, denom);
    e.w = __fdiv_rn(v.w, denom);
    ((float4*)(g_enorm + (size_t)m * DDIM))[t] = e;

    // packed bf16 pairs (elements 4t..4t+3 -> pair indices 2t, 2t+1)
    g_ebf[(size_t)m * NPAIR + 2 * t]     = bf2(e.x, e.y);
    g_ebf[(size_t)m * NPAIR + 2 * t + 1] = bf2(e.z, e.w);

    float p2 = e.x * e.x + e.y * e.y + e.z * e.z + e.w * e.w;
    red[t] = p2;
    __syncthreads();
    for (int s = 128; s > 0; s >>= 1) {
        if (t < s) red[t] += red[t + s];
        __syncthreads();
    }
    if (t == 0) g_se[m] = red[0];
}

// ---------------------------------------------------------------------------
// Fused main kernel:
//  1) screening distance GEMM in packed bf16 (HFMA2 pipe, 2 FLOP/issue),
//     bf16 accumulators flushed to fp32 masters every 32-k tile (err ~0.03)
//  2) exact fp32 re-check of all codes within MARGIN of the screened min;
//     winner via atomicMin on (float_bits(d)<<32 | idx)  -> lowest-index ties
//  3) gather + straight-through output + commitment loss + counts
// Thread layout: 256 threads = 16 ty (rows of 4) x 16 tx2 (codes of 16).
// ---------------------------------------------------------------------------
__global__ __launch_bounds__(256) void vq_main(const float* __restrict__ x,
                                               const float* __restrict__ emb,
                                               float* __restrict__ out) {
    __shared__ __align__(16) uint32_t xsb[KP][ROWS_PER_BLK];  // x bf16 pairs (4KB)
    __shared__ __align__(16) uint32_t esb[KP][MCOD];          // e bf16 pairs (16KB)
    __shared__ float ssx[ROWS_PER_BLK];
    __shared__ u64   skey[ROWS_PER_BLK];
    __shared__ int   sidx[ROWS_PER_BLK];
    __shared__ float sred[256];

    const int t   = threadIdx.x;
    const int ty  = t >> 4;
    const int tx2 = t & 15;
    const size_t rowBase = (size_t)blockIdx.x * ROWS_PER_BLK;

    float accf[4][16];
#pragma unroll
    for (int i = 0; i < 4; i++)
#pragma unroll
        for (int j = 0; j < 16; j++) accf[i][j] = 0.f;

    if (t < ROWS_PER_BLK) skey[t] = ~0ull;

    // Tile-load mapping: x -> thread owns row lr, floats lq*8..lq*8+7;
    // e -> thread t owns code t, 16 pairs per tile.
    const int lr = t >> 2;
    const int lq = t & 3;
    const float* xld = x + (rowBase + lr) * DDIM + lq * 8;
    const uint32_t* eld = g_ebf + (size_t)t * NPAIR;
    float sxp = 0.f;

    for (int k0 = 0; k0 < DDIM / KT; k0++) {
        float4 xa = *(const float4*)(xld + k0 * KT);
        float4 xb = *(const float4*)(xld + k0 * KT + 4);
        sxp = __fmaf_rn(xa.x, xa.x, sxp);
        sxp = __fmaf_rn(xa.y, xa.y, sxp);
        sxp = __fmaf_rn(xa.z, xa.z, sxp);
        sxp = __fmaf_rn(xa.w, xa.w, sxp);
        sxp = __fmaf_rn(xb.x, xb.x, sxp);
        sxp = __fmaf_rn(xb.y, xb.y, sxp);
        sxp = __fmaf_rn(xb.z, xb.z, sxp);
        sxp = __fmaf_rn(xb.w, xb.w, sxp);
        xsb[lq * 4 + 0][lr] = bf2(xa.x, xa.y);
        xsb[lq * 4 + 1][lr] = bf2(xa.z, xa.w);
        xsb[lq * 4 + 2][lr] = bf2(xb.x, xb.y);
        xsb[lq * 4 + 3][lr] = bf2(xb.z, xb.w);

        const uint32_t* ep0 = eld + k0 * KP;
        uint4 e0 = *(const uint4*)(ep0);
        uint4 e1 = *(const uint4*)(ep0 + 4);
        uint4 e2 = *(const uint4*)(ep0 + 8);
        uint4 e3 = *(const uint4*)(ep0 + 12);
        esb[0][t] = e0.x;  esb[1][t] = e0.y;  esb[2][t] = e0.z;  esb[3][t] = e0.w;
        esb[4][t] = e1.x;  esb[5][t] = e1.y;  esb[6][t] = e1.z;  esb[7][t] = e1.w;
        esb[8][t] = e2.x;  esb[9][t] = e2.y;  esb[10][t] = e2.z; esb[11][t] = e2.w;
        esb[12][t] = e3.x; esb[13][t] = e3.y; esb[14][t] = e3.z; esb[15][t] = e3.w;
        __syncthreads();

        uint32_t accb[4][16];
#pragma unroll
        for (int i = 0; i < 4; i++)
#pragma unroll
            for (int j = 0; j < 16; j++) accb[i][j] = 0u;

#pragma unroll
        for (int kk = 0; kk < KP; kk++) {
            uint4 xr4 = *(const uint4*)&xsb[kk][ty * 4];
            uint32_t xr[4] = {xr4.x, xr4.y, xr4.z, xr4.w};
#pragma unroll
            for (int g = 0; g < 4; g++) {
                uint4 ep = *(const uint4*)&esb[kk][g * 64 + tx2 * 4];
#pragma unroll
                for (int i = 0; i < 4; i++) {
                    accb[i][g * 4 + 0] = bffma2(xr[i], ep.x, accb[i][g * 4 + 0]);
                    accb[i][g * 4 + 1] = bffma2(xr[i], ep.y, accb[i][g * 4 + 1]);
                    accb[i][g * 4 + 2] = bffma2(xr[i], ep.z, accb[i][g * 4 + 2]);
                    accb[i][g * 4 + 3] = bffma2(xr[i], ep.w, accb[i][g * 4 + 3]);
                }
            }
        }

        // flush bf16 accumulators (even-k in lo lane, odd-k in hi lane) to fp32
#pragma unroll
        for (int i = 0; i < 4; i++)
#pragma unroll
            for (int j = 0; j < 16; j++) {
                uint32_t p = accb[i][j];
                accf[i][j] += __uint_as_float(p << 16);
                accf[i][j] += __uint_as_float(p & 0xFFFF0000u);
            }
        __syncthreads();
    }

    // per-row sum(x^2): combine the 4 quad-partials (row-constant -> argmin-safe)
    sxp += __shfl_xor_sync(0xffffffffu, sxp, 1);
    sxp += __shfl_xor_sync(0xffffffffu, sxp, 2);
    if (lq == 0) ssx[lr] = sxp;
    __syncthreads();
    const float sx[4] = {ssx[ty * 4 + 0], ssx[ty * 4 + 1],
                         ssx[ty * 4 + 2], ssx[ty * 4 + 3]};

    // screening distances + per-row min
    float rmin[4] = {3.4e38f, 3.4e38f, 3.4e38f, 3.4e38f};
#pragma unroll
    for (int j = 0; j < 16; j++) {
        const int c = (j >> 2) * 64 + tx2 * 4 + (j & 3);
        const float se = g_se[c];
#pragma unroll
        for (int i = 0; i < 4; i++) {
            float d = (se + sx[i]) - 2.0f * accf[i][j];
            accf[i][j] = d;
            rmin[i] = fminf(rmin[i], d);
        }
    }
#pragma unroll
    for (int i = 0; i < 4; i++) {
        rmin[i] = fminf(rmin[i], __shfl_xor_sync(0xffffffffu, rmin[i], 8, 16));
        rmin[i] = fminf(rmin[i], __shfl_xor_sync(0xffffffffu, rmin[i], 4, 16));
        rmin[i] = fminf(rmin[i], __shfl_xor_sync(0xffffffffu, rmin[i], 2, 16));
        rmin[i] = fminf(rmin[i], __shfl_xor_sync(0xffffffffu, rmin[i], 1, 16));
    }

    // exact fp32 re-check of all candidates within MARGIN of the screened min
#pragma unroll
    for (int i = 0; i < 4; i++) {
        const int row = ty * 4 + i;
        const float thr = rmin[i] + MARGIN;
        const float* xr = x + (rowBase + row) * DDIM;
#pragma unroll 1
        for (int j = 0; j < 16; j++) {
            if (accf[i][j] <= thr) {
                const int c = (j >> 2) * 64 + tx2 * 4 + (j & 3);
                const float* er = g_enorm + (size_t)c * DDIM;
                float d0 = 0.f, d1 = 0.f, d2 = 0.f, d3 = 0.f;
                float d4 = 0.f, d5 = 0.f, d6 = 0.f, d7 = 0.f;
                for (int k = 0; k < DDIM; k += 8) {
                    float4 a = *(const float4*)(xr + k);
                    float4 b = *(const float4*)(er + k);
                    float4 a2 = *(const float4*)(xr + k + 4);
                    float4 b2 = *(const float4*)(er + k + 4);
                    d0 = __fmaf_rn(a.x, b.x, d0);
                    d1 = __fmaf_rn(a.y, b.y, d1);
                    d2 = __fmaf_rn(a.z, b.z, d2);
                    d3 = __fmaf_rn(a.w, b.w, d3);
                    d4 = __fmaf_rn(a2.x, b2.x, d4);
                    d5 = __fmaf_rn(a2.y, b2.y, d5);
                    d6 = __fmaf_rn(a2.z, b2.z, d6);
                    d7 = __fmaf_rn(a2.w, b2.w, d7);
                }
                float dot = ((d0 + d1) + (d2 + d3)) + ((d4 + d5) + (d6 + d7));
                float d = __fsub_rn(__fadd_rn(g_se[c], sx[i]),
                                    __fmul_rn(2.0f, dot));
                // distances are ~1000 > 0 -> float bits are order-preserving
                u64 key = ((u64)__float_as_uint(d) << 32) | (uint32_t)c;
                atomicMin(&skey[row], key);
            }
        }
    }
    __syncthreads();

    if (t < ROWS_PER_BLK) {
        sidx[t] = (int)(skey[t] & 0xFFFFFFFFu);
    }
    __syncthreads();
    if (t < ROWS_PER_BLK) atomicAdd(&g_counts[sidx[t]], 1);

    // Gather + straight-through output + loss.
    // quantized_ = fl( fl( fl(x + fl(q-x)) + q ) * 0.5 )  (exactly as reference)
    float lloss = 0.f;
    for (int r = 0; r < ROWS_PER_BLK; ++r) {
        const int idx = sidx[r];
        float4 q  = ((const float4*)(emb + (size_t)idx * DDIM))[t];
        float4 xv = ((const float4*)(x + (rowBase + r) * DDIM))[t];
        float4 o;
        {
            float st = __fadd_rn(xv.x, __fsub_rn(q.x, xv.x));
            o.x = __fmul_rn(__fadd_rn(st, q.x), 0.5f);
            float dd = __fsub_rn(xv.x, q.x);
            lloss = __fmaf_rn(dd, dd, lloss);
        }
        {
            float st = __fadd_rn(xv.y, __fsub_rn(q.y, xv.y));
            o.y = __fmul_rn(__fadd_rn(st, q.y), 0.5f);
            float dd = __fsub_rn(xv.y, q.y);
            lloss = __fmaf_rn(dd, dd, lloss);
        }
        {
            float st = __fadd_rn(xv.z, __fsub_rn(q.z, xv.z));
            o.z = __fmul_rn(__fadd_rn(st, q.z), 0.5f);
            float dd = __fsub_rn(xv.z, q.z);
            lloss = __fmaf_rn(dd, dd, lloss);
        }
        {
            float st = __fadd_rn(xv.w, __fsub_rn(q.w, xv.w));
            o.w = __fmul_rn(__fadd_rn(st, q.w), 0.5f);
            float dd = __fsub_rn(xv.w, q.w);
            lloss = __fmaf_rn(dd, dd, lloss);
        }
        ((float4*)out)[(rowBase + r) * (DDIM / 4) + t] = o;
    }

    sred[t] = lloss;
    __syncthreads();
    for (int s = 128; s > 0; s >>= 1) {
        if (t < s) sred[t] += sred[t + s];
        __syncthreads();
    }
    if (t == 0) atomicAdd(&g_loss, (double)sred[0]);
}

// ---------------------------------------------------------------------------
// Scalars: commitment_loss = mean((x-q)^2), perplexity = exp(-sum p log(p+1e-10))
// ---------------------------------------------------------------------------
__global__ void vq_finalize(float* __restrict__ out) {
    __shared__ float red[256];
    const int t = threadIdx.x;
    float p = (float)g_counts[t] / 25600.0f;
    float term = __fmul_rn(p, logf(__fadd_rn(p, 1e-10f)));
    red[t] = term;
    __syncthreads();
    for (int s = 128; s > 0; s >>= 1) {
        if (t < s) red[t] += red[t + s];
        __syncthreads();
    }
    if (t == 0) {
        out[26214400] = (float)(g_loss / 26214400.0);
        out[26214401] = expf(-red[0]);
    }
}

extern "C" void kernel_launch(void* const* d_in, const int* in_sizes, int n_in,
                              void* d_out, int out_size) {
    const float* x   = (const float*)d_in[0];
    const float* emb = (const float*)d_in[1];
    float* out = (float*)d_out;

    vq_init<<<1, 256>>>();
    vq_normalize<<<MCOD, 256>>>(emb);
    vq_main<<<NTOK / ROWS_PER_BLK, 256>>>(x, emb, out);
    vq_finalize<<<1, 256>>>(out);
}

// round 8
// speedup vs baseline: 1.0546x; 1.0546x over previous
#include <cuda_runtime.h>
#include <cstdint>

// Problem constants (fixed by setup_inputs: N=64, T=400, D=1024, M=256)
#define NTOK 25600
#define DDIM 1024
#define MCOD 256
#define TROWS 64          // rows per CTA
#define KCH 32            // k per chunk
#define NCHK (DDIM / KCH) // 32 chunks
#define MARGIN 0.375f

typedef unsigned long long u64;

// ---------------- device scratch (allocation-free per harness rules) ----------------
__device__ float  g_enorm[MCOD * DDIM];   // fp32 normalized codebook
__device__ float  g_se[MCOD];
__device__ int    g_counts[MCOD];
__device__ double g_loss;

// ---------------- PTX helpers ----------------
static __device__ __forceinline__ uint32_t smem_u32(const void* p) {
    uint32_t a;
    asm("{ .reg .u64 t; cvta.to.shared.u64 t, %1; cvt.u32.u64 %0, t; }" : "=r"(a) : "l"(p));
    return a;
}
static __device__ __forceinline__ void cpasync16(uint32_t dst, const void* src) {
    asm volatile("cp.async.cg.shared.global [%0], [%1], 16;" :: "r"(dst), "l"(src));
}
static __device__ __forceinline__ void cp_commit() {
    asm volatile("cp.async.commit_group;" ::: "memory");
}
template <int N>
static __device__ __forceinline__ void cp_wait() {
    asm volatile("cp.async.wait_group %0;" :: "n"(N) : "memory");
}
// m16n8k8 tf32 MMA, fp32 accumulate (sm_80 baseline feature -> valid on sm_103)
static __device__ __forceinline__ void mma_tf32(float* c, const uint32_t* a,
                                                uint32_t b0, uint32_t b1) {
    asm volatile(
        "mma.sync.aligned.m16n8k8.row.col.f32.tf32.tf32.f32 "
        "{%0,%1,%2,%3}, {%4,%5,%6,%7}, {%8,%9}, {%0,%1,%2,%3};"
        : "+f"(c[0]), "+f"(c[1]), "+f"(c[2]), "+f"(c[3])
        : "r"(a[0]), "r"(a[1]), "r"(a[2]), "r"(a[3]), "r"(b0), "r"(b1));
}

// ---------------------------------------------------------------------------
// Zero accumulators (must run every launch: graph replays reuse globals)
// ---------------------------------------------------------------------------
__global__ void vq_init() {
    int t = threadIdx.x;
    g_counts[t] = 0;
    if (t == 0) g_loss = 0.0;
}

// ---------------------------------------------------------------------------
// emb_norm[m] = emb[m] / (||emb[m]|| + 1e-4);  se[m] = sum(emb_norm[m]^2)
// Replicates reference rounding: fp32 sum -> sqrtf (IEEE) -> +1e-4 -> IEEE div
// ---------------------------------------------------------------------------
__global__ __launch_bounds__(256) void vq_normalize(const float* __restrict__ emb) {
    __shared__ float red[256];
    const int m = blockIdx.x;
    const int t = threadIdx.x;

    float4 v = ((const float4*)(emb + (size_t)m * DDIM))[t];
    float p = v.x * v.x + v.y * v.y + v.z * v.z + v.w * v.w;
    red[t] = p;
    __syncthreads();
    for (int s = 128; s > 0; s >>= 1) {
        if (t < s) red[t] += red[t + s];
        __syncthreads();
    }
    float denom = __fadd_rn(sqrtf(red[0]), 1e-4f);
    __syncthreads();

    float4 e;
    e.x = __fdiv_rn(v.x, denom);
    e.y = __fdiv_rn(v.y, denom);
    e.z = __fdiv_rn(v.z, denom);
    e.w = __fdiv_rn(v.w, denom);
    ((float4*)(g_enorm + (size_t)m * DDIM))[t] = e;

    float p2 = e.x * e.x + e.y * e.y + e.z * e.z + e.w * e.w;
    red[t] = p2;
    __syncthreads();
    for (int s = 128; s > 0; s >>= 1) {
        if (t < s) red[t] += red[t + s];
        __syncthreads();
    }
    if (t == 0) g_se[m] = red[0];
}

// ---------------------------------------------------------------------------
// Main fused kernel:
//  1) tf32 mma.sync screening GEMM: CTA tile 64 rows x 256 codes, K=1024 in
//     32 cp.async double-buffered chunks. 8 warps = 2 rowgroups x 4 colgroups,
//     warp tile 32x64 (2 m-tiles x 8 n-tiles of m16n8k8), fp32 HW accumulate.
//  2) screened distances + per-row approx min; exact fp32 re-check of every
//     code within MARGIN (covers tf32 truncation error); winner by atomicMin
//     on (float_bits(d)<<32 | code) -> exact min with lowest-index ties.
//  3) gather + straight-through output + commitment loss + counts.
// ---------------------------------------------------------------------------
__global__ __launch_bounds__(256, 2) void vq_main(const float* __restrict__ x,
                                                  const float* __restrict__ emb,
                                                  float* __restrict__ out) {
    // dynamic smem: xs[2][8][64][4] floats (16KB) then es[2][8][256][4] (64KB)
    extern __shared__ __align__(16) float dynf[];
    __shared__ float sse[MCOD];
    __shared__ float ssx[TROWS];
    __shared__ unsigned int  sminb[TROWS];
    __shared__ u64  skey[TROWS];
    __shared__ int  sidx[TROWS];
    __shared__ float sred[256];

    const int t = threadIdx.x;
    const int w = t >> 5, l = t & 31;
    const int qr = l >> 2, kl = l & 3;
    const int rbase = (w & 1) * 32;        // rowgroup
    const int cbase = (w >> 1) * 64;       // colgroup
    const size_t rowBase = (size_t)blockIdx.x * TROWS;
    const uint32_t sb = smem_u32(dynf);

    sse[t] = g_se[t];
    if (t < TROWS) { sminb[t] = 0xFFFFFFFFu; skey[t] = ~0ull; }

    float acc[2][8][4];
#pragma unroll
    for (int m = 0; m < 2; m++)
#pragma unroll
        for (int n = 0; n < 8; n++)
#pragma unroll
            for (int c = 0; c < 4; c++) acc[m][n][c] = 0.f;

    // ---- cp.async chunk loader: x -> xs[buf][kq][row][4], e -> es[buf][kq][n][4]
    // x ids 0..511: row=id>>3, kq=id&7 ; e ids 0..2047: n=id>>3, kq=id&7
    const int xrow0 = t >> 3, xkq0 = t & 7;          // id = t
    const int xrow1 = (t + 256) >> 3, xkq1 = t & 7;  // id = t+256
#define ISSUE_CHUNK(BUF, CH)                                                        \
    do {                                                                            \
        cpasync16(sb + (uint32_t)(((BUF) * 2048 + (xkq0 * 64 + xrow0) * 4) * 4),    \
                  x + (rowBase + xrow0) * DDIM + (CH) * KCH + xkq0 * 4);            \
        cpasync16(sb + (uint32_t)(((BUF) * 2048 + (xkq1 * 64 + xrow1) * 4) * 4),    \
                  x + (rowBase + xrow1) * DDIM + (CH) * KCH + xkq1 * 4);            \
        _Pragma("unroll")                                                           \
        for (int j = 0; j < 8; j++) {                                               \
            int id = t + j * 256;                                                   \
            int nn = id >> 3, kq = id & 7;                                          \
            cpasync16(sb + (uint32_t)((4096 + (BUF) * 8192 +                        \
                                       (kq * 256 + nn) * 4) * 4),                   \
                      g_enorm + (size_t)nn * DDIM + (CH) * KCH + kq * 4);           \
        }                                                                           \
        cp_commit();                                                                \
    } while (0)

    ISSUE_CHUNK(0, 0);

    for (int ch = 0; ch < NCHK; ch++) {
        if (ch + 1 < NCHK) {
            ISSUE_CHUNK((ch + 1) & 1, ch + 1);
            cp_wait<1>();
        } else {
            cp_wait<0>();
        }
        __syncthreads();

        const uint32_t* xs = (const uint32_t*)(dynf + (ch & 1) * 2048);
        const uint32_t* es = (const uint32_t*)(dynf + 4096 + (ch & 1) * 8192);
#pragma unroll
        for (int s = 0; s < 4; s++) {
            const uint32_t* xk0 = xs + (2 * s) * 256;
            const uint32_t* xk1 = xs + (2 * s + 1) * 256;
            const uint32_t* ek0 = es + (2 * s) * 1024;
            const uint32_t* ek1 = es + (2 * s + 1) * 1024;
            uint32_t a[2][4];
#pragma unroll
            for (int m = 0; m < 2; m++) {
                const int r0 = rbase + m * 16 + qr;
                a[m][0] = xk0[r0 * 4 + kl];
                a[m][1] = xk0[(r0 + 8) * 4 + kl];
                a[m][2] = xk1[r0 * 4 + kl];
                a[m][3] = xk1[(r0 + 8) * 4 + kl];
            }
#pragma unroll
            for (int n = 0; n < 8; n++) {
                const int nn = cbase + n * 8 + qr;
                uint32_t b0 = ek0[nn * 4 + kl];
                uint32_t b1 = ek1[nn * 4 + kl];
                mma_tf32(acc[0][n], a[0], b0, b1);
                mma_tf32(acc[1][n], a[1], b0, b1);
            }
        }
        __syncthreads();
    }

    // ---- sum(x^2): 4 threads per row, 256 elements each, shfl-combined
    {
        const int row = t >> 2, part = t & 3;
        const float* xr = x + (rowBase + row) * DDIM + part * 256;
        float s = 0.f;
        for (int k = 0; k < 256; k += 4) {
            float4 v = *(const float4*)(xr + k);
            s = __fmaf_rn(v.x, v.x, s);
            s = __fmaf_rn(v.y, v.y, s);
            s = __fmaf_rn(v.z, v.z, s);
            s = __fmaf_rn(v.w, v.w, s);
        }
        s += __shfl_xor_sync(0xffffffffu, s, 1);
        s += __shfl_xor_sync(0xffffffffu, s, 2);
        if (part == 0) ssx[row] = s;
    }
    __syncthreads();

    // ---- screened distances + per-row approx min (distances > 0 -> uint order)
#pragma unroll
    for (int m = 0; m < 2; m++) {
        const int r0 = rbase + m * 16 + qr;       // rows for c0/c1
        const int r1 = r0 + 8;                    // rows for c2/c3
        const float sx0 = ssx[r0], sx1 = ssx[r1];
        float mn0 = 3.4e38f, mn1 = 3.4e38f;
#pragma unroll
        for (int n = 0; n < 8; n++) {
            const int c0 = cbase + n * 8 + 2 * kl;
            const float se0 = sse[c0], se1 = sse[c0 + 1];
            acc[m][n][0] = (se0 + sx0) - 2.0f * acc[m][n][0];
            acc[m][n][1] = (se1 + sx0) - 2.0f * acc[m][n][1];
            acc[m][n][2] = (se0 + sx1) - 2.0f * acc[m][n][2];
            acc[m][n][3] = (se1 + sx1) - 2.0f * acc[m][n][3];
            mn0 = fminf(mn0, fminf(acc[m][n][0], acc[m][n][1]));
            mn1 = fminf(mn1, fminf(acc[m][n][2], acc[m][n][3]));
        }
        atomicMin(&sminb[r0], __float_as_uint(mn0));
        atomicMin(&sminb[r1], __float_as_uint(mn1));
    }
    __syncthreads();

    // ---- exact fp32 re-check of all candidates within MARGIN of screened min
#pragma unroll
    for (int m = 0; m < 2; m++) {
#pragma unroll
        for (int half = 0; half < 2; half++) {
            const int row = rbase + m * 16 + half * 8 + qr;
            const float thr = __uint_as_float(sminb[row]) + MARGIN;
            const float sxv = ssx[row];
            const float* xr = x + (rowBase + row) * DDIM;
#pragma unroll 1
            for (int n = 0; n < 8; n++) {
#pragma unroll 1
                for (int c = 0; c < 2; c++) {
                    if (acc[m][n][half * 2 + c] <= thr) {
                        const int code = cbase + n * 8 + 2 * kl + c;
                        const float* er = g_enorm + (size_t)code * DDIM;
                        float d0 = 0.f, d1 = 0.f, d2 = 0.f, d3 = 0.f;
                        float d4 = 0.f, d5 = 0.f, d6 = 0.f, d7 = 0.f;
                        for (int k = 0; k < DDIM; k += 8) {
                            float4 a = *(const float4*)(xr + k);
                            float4 b = *(const float4*)(er + k);
                            float4 a2 = *(const float4*)(xr + k + 4);
                            float4 b2 = *(const float4*)(er + k + 4);
                            d0 = __fmaf_rn(a.x, b.x, d0);
                            d1 = __fmaf_rn(a.y, b.y, d1);
                            d2 = __fmaf_rn(a.z, b.z, d2);
                            d3 = __fmaf_rn(a.w, b.w, d3);
                            d4 = __fmaf_rn(a2.x, b2.x, d4);
                            d5 = __fmaf_rn(a2.y, b2.y, d5);
                            d6 = __fmaf_rn(a2.z, b2.z, d6);
                            d7 = __fmaf_rn(a2.w, b2.w, d7);
                        }
                        float dot = ((d0 + d1) + (d2 + d3)) + ((d4 + d5) + (d6 + d7));
                        float d = __fsub_rn(__fadd_rn(sse[code], sxv),
                                            __fmul_rn(2.0f, dot));
                        u64 key = ((u64)__float_as_uint(d) << 32) | (uint32_t)code;
                        atomicMin(&skey[row], key);
                    }
                }
            }
        }
    }
    __syncthreads();

    if (t < TROWS) sidx[t] = (int)(skey[t] & 0xFFFFFFFFu);
    __syncthreads();
    if (t < TROWS) atomicAdd(&g_counts[sidx[t]], 1);

    // ---- gather + straight-through output + loss (reference rounding)
    float lloss = 0.f;
    for (int r = 0; r < TROWS; ++r) {
        const int idx = sidx[r];
        float4 q  = ((const float4*)(emb + (size_t)idx * DDIM))[t];
        float4 xv = ((const float4*)(x + (rowBase + r) * DDIM))[t];
        float4 o;
        {
            float st = __fadd_rn(xv.x, __fsub_rn(q.x, xv.x));
            o.x = __fmul_rn(__fadd_rn(st, q.x), 0.5f);
            float dd = __fsub_rn(xv.x, q.x);
            lloss = __fmaf_rn(dd, dd, lloss);
        }
        {
            float st = __fadd_rn(xv.y, __fsub_rn(q.y, xv.y));
            o.y = __fmul_rn(__fadd_rn(st, q.y), 0.5f);
            float dd = __fsub_rn(xv.y, q.y);
            lloss = __fmaf_rn(dd, dd, lloss);
        }
        {
            float st = __fadd_rn(xv.z, __fsub_rn(q.z, xv.z));
            o.z = __fmul_rn(__fadd_rn(st, q.z), 0.5f);
            float dd = __fsub_rn(xv.z, q.z);
            lloss = __fmaf_rn(dd, dd, lloss);
        }
        {
            float st = __fadd_rn(xv.w, __fsub_rn(q.w, xv.w));
            o.w = __fmul_rn(__fadd_rn(st, q.w), 0.5f);
            float dd = __fsub_rn(xv.w, q.w);
            lloss = __fmaf_rn(dd, dd, lloss);
        }
        ((float4*)out)[(rowBase + r) * (DDIM / 4) + t] = o;
    }

    sred[t] = lloss;
    __syncthreads();
    for (int s = 128; s > 0; s >>= 1) {
        if (t < s) sred[t] += sred[t + s];
        __syncthreads();
    }
    if (t == 0) atomicAdd(&g_loss, (double)sred[0]);
}

// ---------------------------------------------------------------------------
// Scalars: commitment_loss = mean((x-q)^2), perplexity = exp(-sum p log(p+1e-10))
// ---------------------------------------------------------------------------
__global__ void vq_finalize(float* __restrict__ out) {
    __shared__ float red[256];
    const int t = threadIdx.x;
    float p = (float)g_counts[t] / 25600.0f;
    float term = __fmul_rn(p, logf(__fadd_rn(p, 1e-10f)));
    red[t] = term;
    __syncthreads();
    for (int s = 128; s > 0; s >>= 1) {
        if (t < s) red[t] += red[t + s];
        __syncthreads();
    }
    if (t == 0) {
        out[26214400] = (float)(g_loss / 26214400.0);
        out[26214401] = expf(-red[0]);
    }
}

extern "C" void kernel_launch(void* const* d_in, const int* in_sizes, int n_in,
                              void* d_out, int out_size) {
    const float* x   = (const float*)d_in[0];
    const float* emb = (const float*)d_in[1];
    float* out = (float*)d_out;

    const int dynBytes = (4096 + 2 * 8192) * 4;   // 80 KB
    cudaFuncSetAttribute(vq_main, cudaFuncAttributeMaxDynamicSharedMemorySize, dynBytes);

    vq_init<<<1, 256>>>();
    vq_normalize<<<MCOD, 256>>>(emb);
    vq_main<<<NTOK / TROWS, 256, dynBytes>>>(x, emb, out);
    vq_finalize<<<1, 256>>>(out);
}